// round 17
// baseline (speedup 1.0000x reference)
#include <cuda_runtime.h>
#include <cuda_bf16.h>
#include <cstdint>

namespace {
constexpr int kT = 8192, kD = 1024, kH = 2048, kE = 8, kK = 2;
constexpr int kCap = 1280, kMaxN = 2560;
constexpr int PA  = kMaxN / 128;  // 20 panels (A rows / act rows)
constexpr int PGU = kH / 128;     // 16 panels (gate/up weight rows)
constexpr int PD  = kD / 128;     // 8 panels (down weight rows)
}

// ---------------- device scratch (device-code references ONLY) -------------
__device__ int   g_topi[kT * kK];
__device__ float g_topw[kT * kK];
__device__ int   g_tok[kE * kMaxN];
__device__ float g_wt [kE * kMaxN];
__device__ int   g_cnt[kE];
// Chunk-blocked swizzled buffers. Block = 8KB: 128 rows x 4 x 16B units,
// unit (r,c) stored at swz(r,c) = r*4 + (c ^ ((r>>1)&3)).
__device__ __align__(128) __nv_bfloat16 g_a  [(size_t)kE * PA  * 2 * 32 * 4096];
__device__ __align__(128) __nv_bfloat16 g_wg [(size_t)kE * PGU * 2 * 32 * 4096];
__device__ __align__(128) __nv_bfloat16 g_wu [(size_t)kE * PGU * 2 * 32 * 4096];
__device__ __align__(128) __nv_bfloat16 g_wd [(size_t)kE * PD  * 2 * 64 * 4096];
__device__ __align__(128) __nv_bfloat16 g_act[(size_t)kE * PA  * 2 * 64 * 4096];

__device__ __forceinline__ int swz(int r, int c) { return r * 4 + (c ^ ((r >> 1) & 3)); }

// ---------------- PTX helpers ----------------
__device__ __forceinline__ uint32_t smem_u32(const void* p) {
    uint32_t a;
    asm("{ .reg .u64 t; cvta.to.shared.u64 t, %1; cvt.u32.u64 %0, t; }" : "=r"(a) : "l"(p));
    return a;
}
__device__ __forceinline__ void mbar_init(uint32_t a, uint32_t c) {
    asm volatile("mbarrier.init.shared.b64 [%0], %1;" :: "r"(a), "r"(c) : "memory");
}
__device__ __forceinline__ void mbar_arrive(uint32_t a) {
    asm volatile("mbarrier.arrive.shared.b64 _, [%0];" :: "r"(a) : "memory");
}
__device__ __forceinline__ void mbar_arrive_tx(uint32_t a, uint32_t bytes) {
    asm volatile("mbarrier.arrive.expect_tx.shared.b64 _, [%0], %1;"
                 :: "r"(a), "r"(bytes) : "memory");
}
__device__ __forceinline__ void mbar_wait(uint32_t a, uint32_t par) {
    asm volatile("{\n\t.reg .pred P;\n\tW_%=:\n\t"
                 "mbarrier.try_wait.parity.acquire.cta.shared::cta.b64 P, [%0], %1, 0x989680;\n\t"
                 "@!P bra.uni W_%=;\n\t}" :: "r"(a), "r"(par) : "memory");
}
__device__ __forceinline__ void bulk_g2s(uint32_t dst, const void* src,
                                         uint32_t bytes, uint32_t mbar) {
    asm volatile("cp.async.bulk.shared::cta.global.mbarrier::complete_tx::bytes "
                 "[%0], [%1], %2, [%3];"
                 :: "r"(dst), "l"(src), "r"(bytes), "r"(mbar) : "memory");
}
__device__ __forceinline__ void ldsm4(uint32_t* r, uint32_t a) {
    asm volatile("ldmatrix.sync.aligned.m8n8.x4.shared.b16 {%0,%1,%2,%3}, [%4];"
                 : "=r"(r[0]), "=r"(r[1]), "=r"(r[2]), "=r"(r[3]) : "r"(a));
}
__device__ __forceinline__ void ldsm2(uint32_t* r, uint32_t a) {
    asm volatile("ldmatrix.sync.aligned.m8n8.x2.shared.b16 {%0,%1}, [%2];"
                 : "=r"(r[0]), "=r"(r[1]) : "r"(a));
}
__device__ __forceinline__ void mma16816(float* d, const uint32_t* a, const uint32_t* b) {
    asm volatile(
        "mma.sync.aligned.m16n8k16.row.col.f32.bf16.bf16.f32 "
        "{%0,%1,%2,%3}, {%4,%5,%6,%7}, {%8,%9}, {%0,%1,%2,%3};"
        : "+f"(d[0]), "+f"(d[1]), "+f"(d[2]), "+f"(d[3])
        : "r"(a[0]), "r"(a[1]), "r"(a[2]), "r"(a[3]), "r"(b[0]), "r"(b[1]));
}
__device__ __forceinline__ uint32_t pack2(__nv_bfloat16 a, __nv_bfloat16 b) {
    __nv_bfloat162 t(a, b);
    return *reinterpret_cast<uint32_t*>(&t);
}

// ---------------- router (verified) ----------------
__global__ __launch_bounds__(256) void router_kernel(const float* __restrict__ x,
                                                     const float* __restrict__ gw) {
    int lane = threadIdx.x & 31, warp = threadIdx.x >> 5;
    int t = blockIdx.x * 8 + warp;
    const float* xr = x + (size_t)t * kD;
    float xv[32];
#pragma unroll
    for (int i = 0; i < 32; i++) xv[i] = xr[lane + 32 * i];
    float lg[kE];
#pragma unroll
    for (int e = 0; e < kE; e++) {
        const float* g = gw + e * kD;
        float s = 0.f;
#pragma unroll
        for (int i = 0; i < 32; i++) s = fmaf(xv[i], g[lane + 32 * i], s);
#pragma unroll
        for (int o = 16; o > 0; o >>= 1) s += __shfl_xor_sync(0xffffffffu, s, o);
        lg[e] = s;
    }
    if (lane == 0) {
        float mx = lg[0];
#pragma unroll
        for (int e = 1; e < kE; e++) mx = fmaxf(mx, lg[e]);
        float p[kE], den = 0.f;
#pragma unroll
        for (int e = 0; e < kE; e++) { p[e] = expf(lg[e] - mx); den += p[e]; }
        int i1 = 0; float p1 = p[0];
#pragma unroll
        for (int e = 1; e < kE; e++) if (p[e] > p1) { p1 = p[e]; i1 = e; }
        int i2 = (i1 == 0) ? 1 : 0; float p2 = p[i2];
#pragma unroll
        for (int e = 0; e < kE; e++) if (e != i1 && p[e] > p2) { p2 = p[e]; i2 = e; }
        float a = p1 / den, b = p2 / den, inv = 1.f / (a + b + 1e-9f);
        g_topi[t * 2] = i1; g_topi[t * 2 + 1] = i2;
        g_topw[t * 2] = a * inv; g_topw[t * 2 + 1] = b * inv;
    }
}

// ---------------- capacity lists (verified) ----------------
__global__ __launch_bounds__(512) void build_lists_kernel() {
    __shared__ int kept[kK][kE];
    int w = threadIdx.x >> 5, lane = threadIdx.x & 31;
    int k = w >> 3, e = w & 7;
    int cnt = 0;
    for (int t0 = 0; t0 < kT; t0 += 32) {
        int sel = (g_topi[(t0 + lane) * 2 + k] == e);
        cnt += __popc(__ballot_sync(0xffffffffu, sel));
    }
    if (lane == 0) kept[k][e] = min(cnt, kCap);
    __syncthreads();
    int off = (k == 0) ? 0 : kept[0][e];
    if (w < kE && lane == 0) g_cnt[w] = kept[0][w] + kept[1][w];
    int rank = 0;
    for (int t0 = 0; t0 < kT; t0 += 32) {
        int t = t0 + lane;
        int sel = (g_topi[t * 2 + k] == e);
        unsigned m = __ballot_sync(0xffffffffu, sel);
        int r = rank + __popc(m & ((1u << lane) - 1u));
        if (sel && r < kCap) {
            g_tok[e * kMaxN + off + r] = t;
            g_wt[e * kMaxN + off + r]  = g_topw[t * 2 + k];
        }
        rank += __popc(m);
    }
}

// ---------------- staging: gather x -> swizzled A blocks ----------------
__global__ __launch_bounds__(256) void stage_x_kernel(const float* __restrict__ x) {
    int er = blockIdx.x * 8 + (threadIdx.x >> 5);
    int lane = threadIdx.x & 31;
    int e = er / kMaxN, m = er % kMaxN;
    if (m >= g_cnt[e]) return;
    const float* s = x + (size_t)g_tok[e * kMaxN + m] * kD;
    int r = m & 127, p = m >> 7;
#pragma unroll
    for (int it = 0; it < 4; it++) {
        int unit = it * 32 + lane;
        int ch = unit >> 2, c = unit & 3;
        float v[8];
        *(float4*)&v[0] = *(const float4*)(s + unit * 8);
        *(float4*)&v[4] = *(const float4*)(s + unit * 8 + 4);
        __nv_bfloat16 hi[8], lo[8];
#pragma unroll
        for (int j = 0; j < 8; j++) {
            hi[j] = __float2bfloat16(v[j]);
            lo[j] = __float2bfloat16(v[j] - __bfloat162float(hi[j]));
        }
        size_t u = (size_t)swz(r, c) * 8;
        size_t bh = ((((size_t)e * PA + p) * 2 + 0) * 32 + ch) * 4096 + u;
        size_t bl = ((((size_t)e * PA + p) * 2 + 1) * 32 + ch) * 4096 + u;
        *(uint4*)(g_a + bh) = *(uint4*)hi;
        *(uint4*)(g_a + bl) = *(uint4*)lo;
    }
}

// ---------------- staging: ALL weights in one launch ----------------
__global__ __launch_bounds__(256) void repack_all_kernel(const float* __restrict__ wg,
                                                         const float* __restrict__ wu,
                                                         const float* __restrict__ wd) {
    int grow = blockIdx.x * 8 + (threadIdx.x >> 5);
    int lane = threadIdx.x & 31;
    const float* src;
    __nv_bfloat16* dst;
    int row, P, CH;
    if (grow < kE * kH)            { src = wg; dst = g_wg; row = grow;               P = PGU; CH = 32; }
    else if (grow < 2 * kE * kH)   { src = wu; dst = g_wu; row = grow - kE * kH;     P = PGU; CH = 32; }
    else                           { src = wd; dst = g_wd; row = grow - 2 * kE * kH; P = PD;  CH = 64; }
    int K = CH * 32;
    int e = row / (P * 128), n = row % (P * 128);
    int r = n & 127, p = n >> 7;
    const float* s = src + (size_t)row * K;
    int units = K / 8;
    for (int unit = lane; unit < units; unit += 32) {
        int ch = unit >> 2, c = unit & 3;
        float v[8];
        *(float4*)&v[0] = *(const float4*)(s + unit * 8);
        *(float4*)&v[4] = *(const float4*)(s + unit * 8 + 4);
        __nv_bfloat16 hi[8], lo[8];
#pragma unroll
        for (int j = 0; j < 8; j++) {
            hi[j] = __float2bfloat16(v[j]);
            lo[j] = __float2bfloat16(v[j] - __bfloat162float(hi[j]));
        }
        size_t u = (size_t)swz(r, c) * 8;
        size_t bh = ((((size_t)e * P + p) * 2 + 0) * CH + ch) * 4096 + u;
        size_t bl = ((((size_t)e * P + p) * 2 + 1) * CH + ch) * 4096 + u;
        *(uint4*)(dst + bh) = *(uint4*)hi;
        *(uint4*)(dst + bl) = *(uint4*)lo;
    }
}

// ---------------------------------------------------------------------------
// Merged GATE+UP GEMM, producer/consumer pipeline, BK=64, register
// double-buffered fragments. Sub-block stream: j -> (chunk=j>>2, blk, kk).
// Prefetch(j+1) overlaps mma(j); stage wait folded into the first sub of a
// chunk; empty-arrive fires at the chunk's LAST ldsm (early producer restart).
// ---------------------------------------------------------------------------
__global__ __launch_bounds__(288, 1) void gu_kernel() {
    constexpr int S = 3;
    constexpr int NC = 48;
    constexpr int SUB = NC * 4;
    extern __shared__ __align__(128) char dsm[];
    __shared__ __align__(8) unsigned long long mbF[S], mbE[S];
    int e = blockIdx.z, ne = g_cnt[e];
    int m0 = blockIdx.x * 128;
    if (m0 >= ne) return;
    int n0 = blockIdx.y * 128;
    int tid = threadIdx.x, warp = tid >> 5, lane = tid & 31;
    uint32_t sb = smem_u32(dsm);
    uint32_t mf = smem_u32(mbF), me = smem_u32(mbE);
    int pa = m0 >> 7, pb = n0 >> 7;

    if (tid == 0)
        for (int s = 0; s < S; s++) { mbar_init(mf + 8 * s, 1); mbar_init(me + 8 * s, 8); }
    __syncthreads();

    if (warp == 8) {
        if (lane == 0) {   // producer
            for (int c = 0; c < NC; c++) {
                int s = c % S;
                mbar_wait(me + 8 * s, ((c / S) & 1) ^ 1);
                int phs = c >> 4, k2 = (c & 15) * 2;
                int apl = (phs == 1), bpl = (phs == 2);
                const __nv_bfloat16* sa = g_a  + ((((size_t)e * PA  + pa) * 2 + apl) * 32 + k2) * 4096;
                const __nv_bfloat16* sg = g_wg + ((((size_t)e * PGU + pb) * 2 + bpl) * 32 + k2) * 4096;
                const __nv_bfloat16* su = g_wu + ((((size_t)e * PGU + pb) * 2 + bpl) * 32 + k2) * 4096;
                uint32_t st = sb + s * 49152;
                mbar_arrive_tx(mf + 8 * s, 49152);
                bulk_g2s(st,         sa, 16384, mf + 8 * s);
                bulk_g2s(st + 16384, sg, 16384, mf + 8 * s);
                bulk_g2s(st + 32768, su, 16384, mf + 8 * s);
            }
        }
        return;
    }

    float accG[4][4][4], accU[4][4][4];
#pragma unroll
    for (int a = 0; a < 4; a++)
#pragma unroll
        for (int b = 0; b < 4; b++)
#pragma unroll
            for (int c = 0; c < 4; c++) { accG[a][b][c] = 0.f; accU[a][b][c] = 0.f; }

    int wm = (warp >> 2) * 64, wn = (warp & 3) * 32;
    int la = lane & 15, lk = lane >> 4;
    int lbr = lane & 7, lbk = (lane >> 3) & 1;

    uint32_t af0[4][4], bg0[4][2], bu0[4][2];
    uint32_t af1[4][4], bg1[4][2], bu1[4][2];

    auto prefetch = [&](int jn, uint32_t (&af)[4][4], uint32_t (&bg)[4][2],
                        uint32_t (&bu)[4][2]) {
        int cn = jn >> 2, blk = (jn >> 1) & 1, kk = jn & 1;
        int s = cn % S;
        if ((jn & 3) == 0) mbar_wait(mf + 8 * s, (cn / S) & 1);
        uint32_t st = sb + s * 49152;
        uint32_t bA = st + blk * 8192;
        uint32_t bG = st + 16384 + blk * 8192;
        uint32_t bU = st + 32768 + blk * 8192;
#pragma unroll
        for (int mt = 0; mt < 4; mt++) {
            int r = wm + mt * 16 + la;
            ldsm4(af[mt], bA + swz(r, kk * 2 + lk) * 16);
        }
#pragma unroll
        for (int nt = 0; nt < 4; nt++) {
            int r = wn + nt * 8 + lbr;
            uint32_t u = swz(r, kk * 2 + lbk) * 16;
            ldsm2(bg[nt], bG + u);
            ldsm2(bu[nt], bU + u);
        }
        if ((jn & 3) == 3 && lane == 0) mbar_arrive(me + 8 * s);
    };
    auto domma = [&](uint32_t (&af)[4][4], uint32_t (&bg)[4][2], uint32_t (&bu)[4][2]) {
#pragma unroll
        for (int mt = 0; mt < 4; mt++)
#pragma unroll
            for (int nt = 0; nt < 4; nt++) {
                mma16816(accG[mt][nt], af[mt], bg[nt]);
                mma16816(accU[mt][nt], af[mt], bu[nt]);
            }
    };

    prefetch(0, af0, bg0, bu0);
    for (int j = 0; j < SUB; j += 2) {
        prefetch(j + 1, af1, bg1, bu1);
        domma(af0, bg0, bu0);
        if (j + 2 < SUB) prefetch(j + 2, af0, bg0, bu0);
        domma(af1, bg1, bu1);
    }

    // epilogue: act = silu(G)*U -> hi/lo blocks (down-GEMM layout)
    int r0 = wm + (lane >> 2);
    int cb0 = wn + (lane & 3) * 2;
#pragma unroll
    for (int mt = 0; mt < 4; mt++)
#pragma unroll
        for (int h = 0; h < 2; h++) {
            int ml = r0 + mt * 16 + h * 8;
#pragma unroll
            for (int nt = 0; nt < 4; nt++) {
                int n = n0 + cb0 + nt * 8;
                float g0 = accG[mt][nt][h * 2], g1 = accG[mt][nt][h * 2 + 1];
                float u0 = accU[mt][nt][h * 2], u1 = accU[mt][nt][h * 2 + 1];
                float v0 = u0 * g0 / (1.f + expf(-g0));
                float v1 = u1 * g1 / (1.f + expf(-g1));
                __nv_bfloat16 h0 = __float2bfloat16(v0), h1 = __float2bfloat16(v1);
                uint32_t hp = pack2(h0, h1);
                uint32_t lp = pack2(__float2bfloat16(v0 - __bfloat162float(h0)),
                                    __float2bfloat16(v1 - __bfloat162float(h1)));
                int ch = n >> 5, cc = (n >> 3) & 3, sub = n & 7;
                size_t u = (size_t)swz(ml, cc) * 8 + sub;
                size_t bh = ((((size_t)e * PA + pa) * 2 + 0) * 64 + ch) * 4096 + u;
                size_t bl = ((((size_t)e * PA + pa) * 2 + 1) * 64 + ch) * 4096 + u;
                *(uint32_t*)(g_act + bh) = hp;
                *(uint32_t*)(g_act + bl) = lp;
            }
        }
}

// ---------------------------------------------------------------------------
// DOWN GEMM + weighted atomic scatter. BK=64, S=4 x 32KB, double-buffered
// fragments, same sub-block streaming.
// ---------------------------------------------------------------------------
__global__ __launch_bounds__(288, 1) void down_kernel(float* __restrict__ out) {
    constexpr int S = 4;
    constexpr int NC = 96;
    constexpr int SUB = NC * 4;
    extern __shared__ __align__(128) char dsm[];
    __shared__ __align__(8) unsigned long long mbF[S], mbE[S];
    int e = blockIdx.z, ne = g_cnt[e];
    int m0 = blockIdx.x * 128;
    if (m0 >= ne) return;
    int n0 = blockIdx.y * 128;
    int tid = threadIdx.x, warp = tid >> 5, lane = tid & 31;
    uint32_t sb = smem_u32(dsm);
    uint32_t mf = smem_u32(mbF), me = smem_u32(mbE);
    int pa = m0 >> 7, pb = n0 >> 7;

    if (tid == 0)
        for (int s = 0; s < S; s++) { mbar_init(mf + 8 * s, 1); mbar_init(me + 8 * s, 8); }
    __syncthreads();

    if (warp == 8) {
        if (lane == 0) {
            for (int c = 0; c < NC; c++) {
                int s = c % S;
                mbar_wait(me + 8 * s, ((c / S) & 1) ^ 1);
                int phs = c >> 5, k2 = (c & 31) * 2;
                int apl = (phs == 1), bpl = (phs == 2);
                const __nv_bfloat16* sa = g_act + ((((size_t)e * PA + pa) * 2 + apl) * 64 + k2) * 4096;
                const __nv_bfloat16* sd = g_wd  + ((((size_t)e * PD + pb) * 2 + bpl) * 64 + k2) * 4096;
                uint32_t st = sb + s * 32768;
                mbar_arrive_tx(mf + 8 * s, 32768);
                bulk_g2s(st,         sa, 16384, mf + 8 * s);
                bulk_g2s(st + 16384, sd, 16384, mf + 8 * s);
            }
        }
        return;
    }

    float acc[4][4][4];
#pragma unroll
    for (int a = 0; a < 4; a++)
#pragma unroll
        for (int b = 0; b < 4; b++)
#pragma unroll
            for (int c = 0; c < 4; c++) acc[a][b][c] = 0.f;

    int wm = (warp >> 2) * 64, wn = (warp & 3) * 32;
    int la = lane & 15, lk = lane >> 4;
    int lbr = lane & 7, lbk = (lane >> 3) & 1;

    uint32_t af0[4][4], bf0[4][2];
    uint32_t af1[4][4], bf1[4][2];

    auto prefetch = [&](int jn, uint32_t (&af)[4][4], uint32_t (&bf)[4][2]) {
        int cn = jn >> 2, blk = (jn >> 1) & 1, kk = jn & 1;
        int s = cn % S;
        if ((jn & 3) == 0) mbar_wait(mf + 8 * s, (cn / S) & 1);
        uint32_t st = sb + s * 32768;
        uint32_t bA = st + blk * 8192;
        uint32_t bB = st + 16384 + blk * 8192;
#pragma unroll
        for (int mt = 0; mt < 4; mt++) {
            int r = wm + mt * 16 + la;
            ldsm4(af[mt], bA + swz(r, kk * 2 + lk) * 16);
        }
#pragma unroll
        for (int nt = 0; nt < 4; nt++) {
            int r = wn + nt * 8 + lbr;
            ldsm2(bf[nt], bB + swz(r, kk * 2 + lbk) * 16);
        }
        if ((jn & 3) == 3 && lane == 0) mbar_arrive(me + 8 * s);
    };
    auto domma = [&](uint32_t (&af)[4][4], uint32_t (&bf)[4][2]) {
#pragma unroll
        for (int mt = 0; mt < 4; mt++)
#pragma unroll
            for (int nt = 0; nt < 4; nt++)
                mma16816(acc[mt][nt], af[mt], bf[nt]);
    };

    prefetch(0, af0, bf0);
    for (int j = 0; j < SUB; j += 2) {
        prefetch(j + 1, af1, bf1);
        domma(af0, bf0);
        if (j + 2 < SUB) prefetch(j + 2, af0, bf0);
        domma(af1, bf1);
    }

    // epilogue: weighted scatter-add
    int r0 = wm + (lane >> 2);
    int cb0 = wn + (lane & 3) * 2;
#pragma unroll
    for (int mt = 0; mt < 4; mt++)
#pragma unroll
        for (int h = 0; h < 2; h++) {
            int ml = r0 + mt * 16 + h * 8;
            if (m0 + ml < ne) {
                int tok  = g_tok[e * kMaxN + m0 + ml];
                float wt = g_wt[e * kMaxN + m0 + ml];
                float* orow = out + (size_t)tok * kD + n0;
#pragma unroll
                for (int nt = 0; nt < 4; nt++) {
                    atomicAdd(&orow[cb0 + nt * 8],     wt * acc[mt][nt][h * 2]);
                    atomicAdd(&orow[cb0 + nt * 8 + 1], wt * acc[mt][nt][h * 2 + 1]);
                }
            }
        }
}

// ---------------- launch ----------------
extern "C" void kernel_launch(void* const* d_in, const int* in_sizes, int n_in,
                              void* d_out, int out_size) {
    (void)in_sizes; (void)n_in;
    const float* x  = (const float*)d_in[0];
    const float* gw = (const float*)d_in[1];
    const float* wg = (const float*)d_in[2];
    const float* wu = (const float*)d_in[3];
    const float* wd = (const float*)d_in[4];
    float* out = (float*)d_out;

    const int GU_SM = 3 * 49152;   // 147456
    const int DN_SM = 4 * 32768;   // 131072
    cudaFuncSetAttribute(gu_kernel,   cudaFuncAttributeMaxDynamicSharedMemorySize, GU_SM);
    cudaFuncSetAttribute(down_kernel, cudaFuncAttributeMaxDynamicSharedMemorySize, DN_SM);

    cudaMemsetAsync(out, 0, (size_t)out_size * sizeof(float));
    router_kernel<<<kT / 8, 256>>>(x, gw);
    build_lists_kernel<<<1, 512>>>();
    stage_x_kernel<<<kE * kMaxN / 8, 256>>>(x);
    repack_all_kernel<<<(2 * kE * kH + kE * kD) / 8, 256>>>(wg, wu, wd);

    dim3 gGU(kMaxN / 128, kH / 128, kE);   // (20, 16, 8)
    gu_kernel<<<gGU, 288, GU_SM>>>();

    dim3 gDN(kMaxN / 128, kD / 128, kE);   // (20, 8, 8)
    down_kernel<<<gDN, 288, DN_SM>>>(out);
}